// round 11
// baseline (speedup 1.0000x reference)
#include <cuda_runtime.h>
#include <cuda_fp16.h>

#define N 192
#define NNN (N * N * N)
#define STEPS 20

#define TX 32          // output tile x (8 quads)
#define TY 16          // output tile y
#define TZ 24          // output tile z (marched) -> grid 6*12*8 = 576 = 1 wave
#define NT 256

#define S0X 40         // c0 row: 10 quads, gx = ox-4 .. ox+35
#define S0Y 20         // c0 rows: gy = oy-2 .. oy+17
#define P0  (S0X * S0Y)
#define S1X 40         // c1 row (valid x = ox-2..ox+33)
#define S1Y 18         // c1 rows: gy = oy-1 .. oy+16
#define P1  (S1X * S1Y)

__device__ float g_scratch[NNN];
__device__ __half2 g_Dh2[NNN / 2];
__device__ __half2 g_Rh2[NNN / 2];

// ---- prepass: (D, rho) fp32 -> fp16 premultiplied by delta_t ----
__global__ __launch_bounds__(256) void convert_maps_kernel(
    const float4* __restrict__ D4, const float4* __restrict__ R4,
    const float* __restrict__ dt_ptr,
    __half2* __restrict__ Dh2, __half2* __restrict__ Rh2)
{
    const int i = blockIdx.x * blockDim.x + threadIdx.x;
    if (i >= NNN / 4) return;
    const float dt = dt_ptr[0] * (1.0f / (float)STEPS);
    const float4 d = D4[i];
    const float4 r = R4[i];
    Dh2[2 * i + 0] = __floats2half2_rn(d.x * dt, d.y * dt);
    Dh2[2 * i + 1] = __floats2half2_rn(d.z * dt, d.w * dt);
    Rh2[2 * i + 0] = __floats2half2_rn(r.x * dt, r.y * dt);
    Rh2[2 * i + 1] = __floats2half2_rn(r.z * dt, r.w * dt);
}

// out = saturate(c + D'*lap + R'*(c - c^2)), D'/R' pre-scaled by dt.
__device__ __forceinline__ float upd(float c, float xl, float xr,
                                     float ym, float yp, float zm, float zp,
                                     float D, float R)
{
    float lap = fmaf(-6.f, c, (xl + xr) + (ym + yp) + (zm + zp));
    return __saturatef(fmaf(D, lap, fmaf(R, fmaf(-c, c, c), c)));
}

__global__ __launch_bounds__(NT, 5) void rd_fused2(
    const float* __restrict__ src, float* __restrict__ dst,
    const __half2* __restrict__ Dh, const __half2* __restrict__ Rh)
{
    __shared__ float s0[4 * P0];   // c0 ring
    __shared__ float s1[4 * P1];   // c1 ring

    const int tid = threadIdx.x;
    const int ox = blockIdx.x * TX;
    const int oy = blockIdx.y * TY;
    const int oz = blockIdx.z * TZ;

    // --- staging: one quad per thread (200 quads, tid<200 active) ---
    const int srow = tid / 10;              // 0..19
    const int sq   = tid - srow * 10;       // 0..9
    const int sgy  = oy - 2 + srow;
    const int sgx  = ox - 4 + sq * 4;
    const bool s_valid = (tid < 200);
    const bool s_inxy  = s_valid && ((unsigned)sgy < N) && ((unsigned)sgx < N);
    float* s_dst_base = s0 + srow * S0X + sq * 4;

    auto loadplane = [&](int k) -> float4 {
        float4 v = make_float4(0.f, 0.f, 0.f, 0.f);
        const int g = oz + k;
        if (s_inxy && (unsigned)g < N)
            v = __ldg((const float4*)(src + ((size_t)g * N + sgy) * N + sgx));
        return v;
    };
    auto commit = [&](int k, float4 v) {
        if (s_valid) *(float4*)(s_dst_base + ((k + 8) & 3) * P0) = v;
    };

    // --- step 1: c1 plane k1, clipped, zero outside domain (180 quads) ---
    auto step1 = [&](int k1) {
        const int g1 = oz + k1;
        float* d1 = s1 + ((k1 + 8) & 3) * P1;
        const float* c0m = s0 + ((k1 - 1 + 8) & 3) * P0;
        const float* c0c = s0 + ((k1 + 8) & 3) * P0;
        const float* c0p = s0 + ((k1 + 1 + 8) & 3) * P0;
        const bool inz = ((unsigned)g1 < N);
        if (tid < 180) {
            const int row = tid / 10;            // 0..17
            const int q   = tid - row * 10;      // 0..9
            const int gy  = oy - 1 + row;
            const int gx  = ox - 4 + q * 4;
            float4 o = make_float4(0.f, 0.f, 0.f, 0.f);
            if (inz && (unsigned)gy < N && (unsigned)gx < N) {
                const int b = (row + 1) * S0X + q * 4;
                const float4 c  = *(const float4*)(c0c + b);
                const float  xl = (q > 0) ? c0c[b - 1] : 0.f;
                const float  xr = (q < 9) ? c0c[b + 4] : 0.f;
                const float4 ym = *(const float4*)(c0c + b - S0X);
                const float4 yp = *(const float4*)(c0c + b + S0X);
                const float4 zm = *(const float4*)(c0m + b);
                const float4 zp = *(const float4*)(c0p + b);
                const int gi = (g1 * N + gy) * N + gx;
                const uint2 du = *(const uint2*)(Dh + (gi >> 1));
                const uint2 ru = *(const uint2*)(Rh + (gi >> 1));
                const float2 d01 = __half22float2(*(const __half2*)&du.x);
                const float2 d23 = __half22float2(*(const __half2*)&du.y);
                const float2 r01 = __half22float2(*(const __half2*)&ru.x);
                const float2 r23 = __half22float2(*(const __half2*)&ru.y);
                o.x = upd(c.x, xl,  c.y, ym.x, yp.x, zm.x, zp.x, d01.x, r01.x);
                o.y = upd(c.y, c.x, c.z, ym.y, yp.y, zm.y, zp.y, d01.y, r01.y);
                o.z = upd(c.z, c.y, c.w, ym.z, yp.z, zm.z, zp.z, d23.x, r23.x);
                o.w = upd(c.w, c.z, xr,  ym.w, yp.w, zm.w, zp.w, d23.y, r23.y);
            }
            *(float4*)(d1 + row * S1X + q * 4) = o;
        }
    };

    // --- step 2: output plane z, always in-domain (128 quads) ---
    auto step2 = [&](int z) {
        const int gz = oz + z;
        const float* c1m = s1 + ((z - 1 + 8) & 3) * P1;
        const float* c1c = s1 + ((z + 8) & 3) * P1;
        const float* c1p = s1 + ((z + 1 + 8) & 3) * P1;
        if (tid < 128) {
            const int row = tid >> 3;            // 0..15
            const int q   = tid & 7;             // 0..7
            const int gy  = oy + row;
            const int gx  = ox + q * 4;
            const int b = (row + 1) * S1X + (q + 1) * 4;
            const float4 c  = *(const float4*)(c1c + b);
            const float  xl = c1c[b - 1];
            const float  xr = c1c[b + 4];
            const float4 ym = *(const float4*)(c1c + b - S1X);
            const float4 yp = *(const float4*)(c1c + b + S1X);
            const float4 zm = *(const float4*)(c1m + b);
            const float4 zp = *(const float4*)(c1p + b);
            const int gi = (gz * N + gy) * N + gx;
            const uint2 du = *(const uint2*)(Dh + (gi >> 1));
            const uint2 ru = *(const uint2*)(Rh + (gi >> 1));
            const float2 d01 = __half22float2(*(const __half2*)&du.x);
            const float2 d23 = __half22float2(*(const __half2*)&du.y);
            const float2 r01 = __half22float2(*(const __half2*)&ru.x);
            const float2 r23 = __half22float2(*(const __half2*)&ru.y);
            float4 o;
            o.x = upd(c.x, xl,  c.y, ym.x, yp.x, zm.x, zp.x, d01.x, r01.x);
            o.y = upd(c.y, c.x, c.z, ym.y, yp.y, zm.y, zp.y, d01.y, r01.y);
            o.z = upd(c.z, c.y, c.w, ym.z, yp.z, zm.z, zp.z, d23.x, r23.x);
            o.w = upd(c.w, c.z, xr,  ym.w, yp.w, zm.w, zp.w, d23.y, r23.y);
            *(float4*)(dst + gi) = o;
        }
    };

    // ---- prologue: s0 planes -2,-1 in smem; plane 0 in registers ----
    commit(-2, loadplane(-2));
    commit(-1, loadplane(-1));
    float4 r = loadplane(0);

    // ---- pipelined march: ONE sync per iteration ----
    // Invariant at iter top: s0 holds planes z-1..z+2 (after commit), regs r = plane z+3's
    // data is loaded inside the iter. commit(z+3) overwrites the slot of dead plane z-1.
    #pragma unroll 1
    for (int z = -3; z < TZ; ++z) {
        if (z + 3 <= TZ + 1) commit(z + 3, r);
        __syncthreads();
        if (z + 4 <= TZ + 1) r = loadplane(z + 4);   // in flight during compute
        if (z + 2 <= TZ)     step1(z + 2);
        if (z >= 0)          step2(z);
    }
}

extern "C" void kernel_launch(void* const* d_in, const int* in_sizes, int n_in,
                              void* d_out, int out_size)
{
    const float*  c_init = (const float*)d_in[0];
    const float4* D_map  = (const float4*)d_in[1];
    const float4* rho    = (const float4*)d_in[2];
    const float*  dt     = (const float*)d_in[3];
    float* out = (float*)d_out;

    float* scratch = nullptr;
    __half2* Dh2 = nullptr;
    __half2* Rh2 = nullptr;
    cudaGetSymbolAddress((void**)&scratch, g_scratch);
    cudaGetSymbolAddress((void**)&Dh2, g_Dh2);
    cudaGetSymbolAddress((void**)&Rh2, g_Rh2);

    convert_maps_kernel<<<(NNN / 4 + 255) / 256, 256>>>(D_map, rho, dt, Dh2, Rh2);

    dim3 block(NT, 1, 1);
    dim3 grid(N / TX, N / TY, N / TZ);   // (6, 12, 8) = 576 blocks = 1 wave

    // 10 fused launches = 20 steps; launch 9 (odd) lands in d_out.
    const float* s = c_init;
    for (int i = 0; i < STEPS / 2; ++i) {
        float* dptr = (i & 1) ? out : scratch;
        rd_fused2<<<grid, block>>>(s, dptr, Dh2, Rh2);
        s = dptr;
    }
}

// round 12
// speedup vs baseline: 1.4636x; 1.4636x over previous
#include <cuda_runtime.h>
#include <cuda_fp16.h>

#define N 192
#define NV (N / 4)          // 48 float4 per x-row
#define NNN (N * N * N)
#define STEPS 20

// Ping buffer (pong is d_out).
__device__ float4 g_scratch4[NNN / 4];
// Interleaved fp16 maps, premultiplied by delta_t: per quad i,
// 16B record = {D0,D1,D2,D3,R0,R1,R2,R3} as halves.
__device__ uint4 g_DR[NNN / 4];

// ---- prepass: (D, rho) fp32 -> interleaved fp16 * delta_t ----
__global__ __launch_bounds__(256) void convert_maps_kernel(
    const float4* __restrict__ D4, const float4* __restrict__ R4,
    const float* __restrict__ dt_ptr, uint4* __restrict__ DR)
{
    const int i = blockIdx.x * blockDim.x + threadIdx.x;
    if (i >= NNN / 4) return;
    const float dt = dt_ptr[0] * (1.0f / (float)STEPS);
    const float4 d = D4[i];
    const float4 r = R4[i];
    uint4 o;
    *(__half2*)&o.x = __floats2half2_rn(d.x * dt, d.y * dt);
    *(__half2*)&o.y = __floats2half2_rn(d.z * dt, d.w * dt);
    *(__half2*)&o.z = __floats2half2_rn(r.x * dt, r.y * dt);
    *(__half2*)&o.w = __floats2half2_rn(r.z * dt, r.w * dt);
    DR[i] = o;
}

// out = saturate(c + D'*lap + R'*(c - c^2)); D'/R' pre-scaled by dt.
__device__ __forceinline__ float upd(float c, float xl, float xr,
                                     float ym, float yp, float zm, float zp,
                                     float D, float R)
{
    float lap = fmaf(-6.f, c, (xl + xr) + (ym + yp) + (zm + zp));
    return __saturatef(fmaf(D, lap, fmaf(R, fmaf(-c, c, c), c)));
}

__device__ __forceinline__ float4 quad_upd(float4 c, float xl, float xr,
                                           float4 ym, float4 yp,
                                           float4 zm, float4 zp, uint4 dr)
{
    const float2 d01 = __half22float2(*(const __half2*)&dr.x);
    const float2 d23 = __half22float2(*(const __half2*)&dr.y);
    const float2 r01 = __half22float2(*(const __half2*)&dr.z);
    const float2 r23 = __half22float2(*(const __half2*)&dr.w);
    float4 o;
    o.x = upd(c.x, xl,  c.y, ym.x, yp.x, zm.x, zp.x, d01.x, r01.x);
    o.y = upd(c.y, c.x, c.z, ym.y, yp.y, zm.y, zp.y, d01.y, r01.y);
    o.z = upd(c.z, c.y, c.w, ym.z, yp.z, zm.z, zp.z, d23.x, r23.x);
    o.w = upd(c.w, c.z, xr,  ym.w, yp.w, zm.w, zp.w, d23.y, r23.y);
    return o;
}

// Each thread computes two quads stacked in y (rows y0, y0+1).
__global__ __launch_bounds__(192) void rd_step_kernel(
    const float4* __restrict__ src4,
    float4* __restrict__ dst4,
    const uint4* __restrict__ DR)
{
    const int tx = threadIdx.x;                                  // 0..47
    const int y0 = (blockIdx.y * blockDim.y + threadIdx.y) * 2;  // even, 0..190
    const int z  = blockIdx.z;                                   // 0..191
    const int idxA = (z * N + y0) * NV + tx;
    const int idxB = idxA + NV;

    const float* src = (const float*)src4;
    const float4 zero = make_float4(0.f, 0.f, 0.f, 0.f);

    // Wide loads, front-batched for MLP.
    const float4 cA = src4[idxA];
    const float4 cB = src4[idxB];
    const float4 ym = (y0 > 0)      ? src4[idxA - NV]     : zero;  // row y0-1
    const float4 yp = (y0 < N - 2)  ? src4[idxB + NV]     : zero;  // row y0+2
    const float4 zmA = (z > 0)      ? src4[idxA - NV * N] : zero;
    const float4 zmB = (z > 0)      ? src4[idxB - NV * N] : zero;
    const float4 zpA = (z < N - 1)  ? src4[idxA + NV * N] : zero;
    const float4 zpB = (z < N - 1)  ? src4[idxB + NV * N] : zero;
    const uint4 drA = DR[idxA];
    const uint4 drB = DR[idxB];
    const int baseA = idxA * 4, baseB = idxB * 4;
    const float lA = (tx > 0)      ? src[baseA - 1] : 0.f;
    const float rA = (tx < NV - 1) ? src[baseA + 4] : 0.f;
    const float lB = (tx > 0)      ? src[baseB - 1] : 0.f;
    const float rB = (tx < NV - 1) ? src[baseB + 4] : 0.f;

    // Row A: down-neighbor ym, up-neighbor cB. Row B: down cA, up yp.
    dst4[idxA] = quad_upd(cA, lA, rA, ym, cB, zmA, zpA, drA);
    dst4[idxB] = quad_upd(cB, lB, rB, cA, yp, zmB, zpB, drB);
}

extern "C" void kernel_launch(void* const* d_in, const int* in_sizes, int n_in,
                              void* d_out, int out_size)
{
    const float4* c_init = (const float4*)d_in[0];
    const float4* D_map  = (const float4*)d_in[1];
    const float4* rho    = (const float4*)d_in[2];
    const float*  dt     = (const float*)d_in[3];
    float4* out = (float4*)d_out;

    float4* scratch = nullptr;
    uint4* DR = nullptr;
    cudaGetSymbolAddress((void**)&scratch, g_scratch4);
    cudaGetSymbolAddress((void**)&DR, g_DR);

    convert_maps_kernel<<<(NNN / 4 + 255) / 256, 256>>>(D_map, rho, dt, DR);

    dim3 block(NV, 4, 1);       // 48 x 4 = 192 threads, 8 y-rows per block
    dim3 grid(1, N / 8, N);     // (1, 24, 192)

    const float4* src = c_init;
    for (int i = 0; i < STEPS; ++i) {
        float4* dst = (i & 1) ? out : scratch;
        rd_step_kernel<<<grid, block>>>(src, dst, DR);
        src = dst;
    }
}